// round 1
// baseline (speedup 1.0000x reference)
#include <cuda_runtime.h>
#include <cuda_bf16.h>
#include <math.h>

#define H 1024
#define E 64
#define MAXN 32768
#define BM 64
#define BK 32
#define PAD 68   // row stride (floats) for k-major smem tiles; 272B = 16B aligned

// ---------------- scratch (no allocation allowed) ----------------
__device__ float    g_logits[MAXN * E];   // logits -> probs (in place)
__device__ float    g_Rt[(size_t)E * MAXN]; // expert-major R for column selection
__device__ float    g_fi[E];
__device__ float    g_pi[E];
__device__ unsigned g_thresh[E];

__device__ __forceinline__ unsigned mono_key(float f) {
    unsigned u = __float_as_uint(f);
    return (u & 0x80000000u) ? ~u : (u | 0x80000000u);
}

// ---------------- init ----------------
__global__ void init_kernel() {
    int t = threadIdx.x;
    if (t < E) { g_fi[t] = 0.f; g_pi[t] = 0.f; }
}

// ---------------- kernel A: fp32 GEMM  logits[n][e] = x[n][:] . w[e][:] ----------------
__global__ __launch_bounds__(256) void gemm_kernel(const float* __restrict__ x,
                                                   const float* __restrict__ w,
                                                   int N) {
    __shared__ __align__(16) float As[BK * PAD]; // [k][n]
    __shared__ __align__(16) float Bs[BK * PAD]; // [k][e]
    int n0 = blockIdx.x * BM;
    int t  = threadIdx.x;
    int te = t & 15;       // expert group 0..15
    int tn = t >> 4;       // token group 0..15
    int lr = t >> 3;       // load row 0..31
    int lc = (t & 7) * 4;  // load col 0,4,...,28

    float acc[4][4];
#pragma unroll
    for (int i = 0; i < 4; i++)
#pragma unroll
        for (int j = 0; j < 4; j++) acc[i][j] = 0.f;

    for (int h0 = 0; h0 < H; h0 += BK) {
        // load x tile (64 tokens x 32 h), transpose to k-major
#pragma unroll
        for (int rr = 0; rr < 2; rr++) {
            int r = lr + rr * 32;
            float4 v = *(const float4*)(x + (size_t)(n0 + r) * H + h0 + lc);
            As[(lc + 0) * PAD + r] = v.x;
            As[(lc + 1) * PAD + r] = v.y;
            As[(lc + 2) * PAD + r] = v.z;
            As[(lc + 3) * PAD + r] = v.w;
        }
        // load w tile (64 experts x 32 h), transpose to k-major
#pragma unroll
        for (int rr = 0; rr < 2; rr++) {
            int r = lr + rr * 32;
            float4 v = *(const float4*)(w + (size_t)r * H + h0 + lc);
            Bs[(lc + 0) * PAD + r] = v.x;
            Bs[(lc + 1) * PAD + r] = v.y;
            Bs[(lc + 2) * PAD + r] = v.z;
            Bs[(lc + 3) * PAD + r] = v.w;
        }
        __syncthreads();
#pragma unroll
        for (int k = 0; k < BK; k++) {
            float4 a = *(const float4*)&As[k * PAD + tn * 4];
            float4 b = *(const float4*)&Bs[k * PAD + te * 4];
            float av[4] = {a.x, a.y, a.z, a.w};
            float bv[4] = {b.x, b.y, b.z, b.w};
#pragma unroll
            for (int i = 0; i < 4; i++)
#pragma unroll
                for (int j = 0; j < 4; j++) acc[i][j] += av[i] * bv[j];
        }
        __syncthreads();
    }
#pragma unroll
    for (int i = 0; i < 4; i++) {
        float4 o = make_float4(acc[i][0], acc[i][1], acc[i][2], acc[i][3]);
        *(float4*)(g_logits + (size_t)(n0 + tn * 4 + i) * E + te * 4) = o;
    }
}

// ---------------- kernel B: softmax + rank/threshold routing (1 warp / token) ----------------
__global__ __launch_bounds__(256) void router_kernel(float* __restrict__ out_top1, int N) {
    int gwarp = (blockIdx.x * blockDim.x + threadIdx.x) >> 5;
    int lane  = threadIdx.x & 31;
    if (gwarp >= N) return;
    float* row = g_logits + (size_t)gwarp * E;
    float l0 = row[lane];
    float l1 = row[lane + 32];
    float m = fmaxf(l0, l1);
#pragma unroll
    for (int o = 16; o; o >>= 1) m = fmaxf(m, __shfl_xor_sync(0xFFFFFFFFu, m, o));
    float e0 = expf(l0 - m), e1 = expf(l1 - m);
    float s = e0 + e1;
#pragma unroll
    for (int o = 16; o; o >>= 1) s += __shfl_xor_sync(0xFFFFFFFFu, s, o);
    float p0 = e0 / s, p1 = e1 / s;

    int c0 = 0, c1 = 0;
    float S0 = 0.f, S1 = 0.f;
#pragma unroll
    for (int j = 0; j < 64; j++) {
        float pj = __shfl_sync(0xFFFFFFFFu, (j < 32) ? p0 : p1, j & 31);
        bool g0 = (pj > p0) || (pj == p0 && j < lane);
        bool g1 = (pj > p1) || (pj == p1 && j < lane + 32);
        if (g0) { c0++; S0 += pj; }
        if (g1) { c1++; S1 += pj; }
    }
    float R0 = (S0 < 0.9f) ? (p0 - (float)(c0 + 1)) : -1e9f;
    float R1 = (S1 < 0.9f) ? (p1 - (float)(c1 + 1)) : -1e9f;
    g_Rt[(size_t)lane * N + gwarp]        = R0;
    g_Rt[(size_t)(lane + 32) * N + gwarp] = R1;
    row[lane]      = p0;   // overwrite logits with probs
    row[lane + 32] = p1;
    if (c0 == 0) {
        out_top1[gwarp] = (float)lane;
        atomicAdd(&g_fi[lane], 1.f);
        atomicAdd(&g_pi[lane], p0);
    }
    if (c1 == 0) {
        out_top1[gwarp] = (float)(lane + 32);
        atomicAdd(&g_fi[lane + 32], 1.f);
        atomicAdd(&g_pi[lane + 32], p1);
    }
}

// ---------------- kernel C: per-expert radix select of C-th largest R ----------------
__global__ __launch_bounds__(256) void select_kernel(int N, int C) {
    int e = blockIdx.x;
    const float* col = g_Rt + (size_t)e * N;
    __shared__ unsigned hist[256];
    __shared__ unsigned s_prefix;
    __shared__ int s_remaining;
    int tid = threadIdx.x;
    if (tid == 0) { s_prefix = 0u; s_remaining = C; }
    __syncthreads();
    for (int shift = 24; shift >= 0; shift -= 8) {
        hist[tid] = 0u;
        __syncthreads();
        unsigned prefix = s_prefix;
        for (int i = tid; i < N; i += 256) {
            unsigned key = mono_key(col[i]);
            bool match = (shift == 24) || ((key >> (shift + 8)) == prefix);
            if (match) atomicAdd(&hist[(key >> shift) & 0xFFu], 1u);
        }
        __syncthreads();
        if (tid == 0) {
            int rem = s_remaining;
            int b = 255;
            while (b > 0 && (int)hist[b] < rem) { rem -= (int)hist[b]; b--; }
            s_prefix = (s_prefix << 8) | (unsigned)b;
            s_remaining = rem;
        }
        __syncthreads();
    }
    if (tid == 0) g_thresh[e] = s_prefix;
}

// ---------------- kernel D: finalize mask + scores (32 tokens x 64 experts / block) ----------------
__global__ __launch_bounds__(256) void finalize_kernel(float* __restrict__ mask_out,
                                                       float* __restrict__ scores_out,
                                                       int N) {
    __shared__ float Rs[64][33];
    __shared__ unsigned th[64];
    int n0 = blockIdx.x * 32;
    int t = threadIdx.x;
    if (t < 64) th[t] = g_thresh[t];
    for (int idx = t; idx < 64 * 32; idx += 256) {
        int e = idx >> 5, j = idx & 31;
        Rs[e][j] = g_Rt[(size_t)e * N + n0 + j];
    }
    __syncthreads();
#pragma unroll
    for (int i = 0; i < 8; i++) {
        int o = i * 256 + t;       // 0..2047
        int nl = o >> 6, e = o & 63;
        float R = Rs[e][nl];
        bool keep = (R > -1e8f) && (mono_key(R) >= th[e]);
        size_t go = (size_t)n0 * 64 + o;
        float p = g_logits[go];    // probs now
        mask_out[go]   = keep ? 1.f : 0.f;
        scores_out[go] = keep ? p : 0.f;
    }
}

// ---------------- kernel E: aux loss ----------------
__global__ void aux_kernel(float* __restrict__ out_aux, int N) {
    int l = threadIdx.x;
    float v = g_fi[l] * g_pi[l] + g_fi[l + 32] * g_pi[l + 32];
#pragma unroll
    for (int o = 16; o; o >>= 1) v += __shfl_xor_sync(0xFFFFFFFFu, v, o);
    if (l == 0) out_aux[0] = (float)E * (v / ((float)N * (float)N)) * 0.01f;
}

// ---------------- launch ----------------
extern "C" void kernel_launch(void* const* d_in, const int* in_sizes, int n_in,
                              void* d_out, int out_size) {
    const float* x = (const float*)d_in[0];
    const float* w = (const float*)d_in[1];
    int N = in_sizes[0] / H;            // 32768
    int C = (N + E - 1) / E;            // capacity (factor 1.0)
    if (C > N) C = N;

    float* out      = (float*)d_out;
    float* mask_out = out;                             // N*E
    float* scr_out  = out + (size_t)N * E;             // N*E
    float* aux_out  = out + (size_t)2 * N * E;         // 1
    float* top1_out = out + (size_t)2 * N * E + 1;     // N

    init_kernel<<<1, 64>>>();
    gemm_kernel<<<N / BM, 256>>>(x, w, N);
    router_kernel<<<(N * 32) / 256, 256>>>(top1_out, N);
    select_kernel<<<E, 256>>>(N, C);
    finalize_kernel<<<N / 32, 256>>>(mask_out, scr_out, N);
    aux_kernel<<<1, 32>>>(aux_out, N);
}